// round 13
// baseline (speedup 1.0000x reference)
#include <cuda_runtime.h>
#include <cstdint>

#define WDIM 256
#define HDIM 256
#define DPT  8
#define NBLK (2 * DPT)                  // 16 (branch,depth) blocks
#define NROWS (NBLK * WDIM)             // 4096 hull rows
#define JGCAP 64                        // max line-groups of 4 (256 lines)
#define NEG_INF __int_as_float(0xff800000)
#define POS_INF __int_as_float(0x7f800000)
#define NB 2                            // batches per scan CTA

// Hull lines in groups of 4: [blk][jg][w] as float4 (coalesced LDG.128).
__device__ float4 g_m4[NBLK * JGCAP * WDIM];    // 4 MB
__device__ float4 g_b4[NBLK * JGCAP * WDIM];    // 4 MB
__device__ int    g_cnt[NBLK * WDIM];           // per-row padded count (x4)
__device__ int    g_jmax[NBLK];                 // per-block max count (atomicMax,
                                                // idempotent across replays)

// ─────────── Kernel 1: upper-envelope hull via warp-parallel Jarvis march ───
__global__ __launch_bounds__(256)
void hull_kernel(const float* __restrict__ M1, const float* __restrict__ B1,
                 const float* __restrict__ M2, const float* __restrict__ B2)
{
    const int tid  = threadIdx.x;
    const int wid  = tid >> 5;
    const int lane = tid & 31;
    const int row  = blockIdx.x * 8 + wid;      // 0..4095
    const int br   = row >> 11;
    const int d    = (row >> 8) & 7;
    const int w    = row & 255;

    const float* Msrc = (br ? M2 : M1) + (d * WDIM + w) * HDIM;
    const float* Bsrc = (br ? B2 : B1) + (d * WDIM + w) * HDIM;

    float m[8], b[8];
#pragma unroll
    for (int r = 0; r < 8; r++) {
        m[r] = Msrc[r * 32 + lane];     // coalesced across the warp
        b[r] = Bsrc[r * 32 + lane];
    }

    // Start line: argmax slope, tie-break max intercept.
    float cm = m[0], cb = b[0];
#pragma unroll
    for (int r = 1; r < 8; r++)
        if (m[r] > cm || (m[r] == cm && b[r] > cb)) { cm = m[r]; cb = b[r]; }
#pragma unroll
    for (int o = 16; o > 0; o >>= 1) {
        const float om = __shfl_xor_sync(~0u, cm, o);
        const float ob = __shfl_xor_sync(~0u, cb, o);
        if (om > cm || (om == cm && ob > cb)) { cm = om; cb = ob; }
    }

    const int blk = br * DPT + d;
    float* hm = (float*)g_m4;
    float* hb = (float*)g_b4;
    auto hidx = [&](int j) -> size_t {
        return ((size_t)(blk * JGCAP + (j >> 2)) * WDIM + w) * 4 + (j & 3);
    };

    if (lane == 0) { hm[hidx(0)] = cm; hb[hidx(0)] = cb; }
    const float m0 = cm, b0 = cb;
    int k = 1;

    while (k < HDIM) {
        // Candidates: m_j < cm. Crossing q with current line; pick max q,
        // tie-break min slope (skips collinear intermediates).
        float bq = NEG_INF, bm = POS_INF, bb = 0.0f;
#pragma unroll
        for (int r = 0; r < 8; r++) {
            const float dm   = cm - m[r];
            const bool  cand = dm > 0.0f;
            const float qx   = cand ? __fdividef(b[r] - cb, dm) : NEG_INF;
            const float mx   = cand ? m[r] : POS_INF;
            if (qx > bq || (qx == bq && mx < bm)) { bq = qx; bm = mx; bb = b[r]; }
        }
#pragma unroll
        for (int o = 16; o > 0; o >>= 1) {
            const float oq = __shfl_xor_sync(~0u, bq, o);
            const float om = __shfl_xor_sync(~0u, bm, o);
            const float ob = __shfl_xor_sync(~0u, bb, o);
            if (oq > bq || (oq == bq && om < bm)) { bq = oq; bm = om; bb = ob; }
        }
        if (bq == NEG_INF) break;       // no line with smaller slope remains
        cm = bm; cb = bb;
        if (lane == 0) { hm[hidx(k)] = cm; hb[hidx(k)] = cb; }
        k++;
    }

    // Pad to a multiple of 4 with duplicates of line 0 (harmless under max).
    const int kpad = (k + 3) & ~3;
    for (int j = k + lane; j < kpad; j += 32) {
        hm[hidx(j)] = m0;
        hb[hidx(j)] = b0;
    }
    if (lane == 0) {
        g_cnt[blk * WDIM + w] = kpad;
        atomicMax(&g_jmax[blk], kpad);   // zero-init global; idempotent
    }
}

// ─────────── Kernel 2: scan, 2-warp CTA splits the w dimension ──────────────
// CTA (64 thr) owns NB batches of one branch. Warp h covers w-rows
// h*128 + 32r + lane (r<4). One syncthreads per depth merges the two halves.
__global__ __launch_bounds__(64)
void scan_kernel(const float* __restrict__ val, float* __restrict__ out)
{
    __shared__ float part[2][2][NB];    // [depth&1][warp][batch]

    const int lane   = threadIdx.x & 31;
    const int h      = threadIdx.x >> 5;        // warp id in CTA: 0/1
    const int cta    = blockIdx.x;              // 0..1023
    const int br     = cta >> 9;
    const int batch0 = (cta & 511) * NB;

    float q[NB];
#pragma unroll
    for (int i = 0; i < NB; i++) q[i] = val[batch0 + i];

    // Hoist per-depth uniform group counts off the critical path.
    int km[DPT];
#pragma unroll
    for (int d = 0; d < DPT; d++)
        km[d] = g_jmax[br * DPT + d] >> 2;

    const int wrow = h * 128 + lane;            // this lane's first row

    // Per-row padded counts for depth 0 (prefetched each depth thereafter).
    int kr[4];
#pragma unroll
    for (int r = 0; r < 4; r++)
        kr[r] = g_cnt[(br * DPT + 0) * WDIM + wrow + 32 * r];

    for (int d = 0; d < DPT; d++) {
        const int blk = br * DPT + d;
        const int JG  = km[d];

        // Prefetch next depth's counts (q-independent; hides L2 latency).
        int krn[4];
        if (d + 1 < DPT) {
#pragma unroll
            for (int r = 0; r < 4; r++)
                krn[r] = g_cnt[(blk + 1) * WDIM + wrow + 32 * r];
        }

        float rm[4][NB];
#pragma unroll
        for (int r = 0; r < 4; r++)
#pragma unroll
            for (int i = 0; i < NB; i++) rm[r][i] = NEG_INF;

        const size_t gb0 = (size_t)blk * JGCAP * WDIM + wrow;
#pragma unroll 2
        for (int jg = 0; jg < JG; jg++) {
            const size_t gb = gb0 + (size_t)jg * WDIM;
#pragma unroll
            for (int r = 0; r < 4; r++) {
                float4 m4 = g_m4[gb + 32 * r];   // coalesced LDG.128
                float4 b4 = g_b4[gb + 32 * r];
                if (jg * 4 >= kr[r]) {           // tail group: neutral lines
                    m4.x = m4.y = m4.z = m4.w = 0.0f;
                    b4.x = b4.y = b4.z = b4.w = NEG_INF;
                }
#pragma unroll
                for (int i = 0; i < NB; i++) {
                    float t = fmaxf(fmaf(q[i], m4.x, b4.x),
                                    fmaf(q[i], m4.y, b4.y));
                    t = fmaxf(t, fmaf(q[i], m4.z, b4.z));
                    t = fmaxf(t, fmaf(q[i], m4.w, b4.w));
                    rm[r][i] = fmaxf(rm[r][i], t);
                }
            }
        }

        // min over this warp's half: 4 rows then 5-step butterfly.
#pragma unroll
        for (int i = 0; i < NB; i++) {
            float a = fminf(fminf(rm[0][i], rm[1][i]),
                            fminf(rm[2][i], rm[3][i]));
#pragma unroll
            for (int o = 16; o > 0; o >>= 1)
                a = fminf(a, __shfl_xor_sync(~0u, a, o));
            if (lane == 0) part[d & 1][h][i] = a;
        }
        __syncthreads();    // publish halves; prior buffer reads are older
#pragma unroll
        for (int i = 0; i < NB; i++)
            q[i] = fminf(part[d & 1][0][i], part[d & 1][1][i]);

#pragma unroll
        for (int r = 0; r < 4; r++) kr[r] = krn[r];
    }

    if (threadIdx.x == 0) {
#pragma unroll
        for (int i = 0; i < NB; i++)
            out[br * 1024 + batch0 + i] = q[i];
    }
}

extern "C" void kernel_launch(void* const* d_in, const int* in_sizes, int n_in,
                              void* d_out, int out_size)
{
    const float* val = (const float*)d_in[0];
    const float* M1  = (const float*)d_in[1];
    const float* B1  = (const float*)d_in[2];
    const float* M2  = (const float*)d_in[3];
    const float* B2  = (const float*)d_in[4];
    float* out = (float*)d_out;

    hull_kernel<<<NROWS / 8, 256>>>(M1, B1, M2, B2);
    scan_kernel<<<1024, 64>>>(val, out);
}